// round 11
// baseline (speedup 1.0000x reference)
#include <cuda_runtime.h>
#include <cstdint>
#include <math.h>

#define BATCH 4
#define SEQ   2048
#define EMB   512
#define NH    8
#define HD    64
#define MROWS (BATCH*SEQ)   // 8192

// Scratch (device globals: allocation-free per harness rules)
__device__ float g_Q[BATCH*NH*SEQ*HD];   // (b,h,n,d)
__device__ float g_K[BATCH*NH*SEQ*HD];
__device__ float g_V[BATCH*NH*SEQ*HD];
__device__ float g_AO[BATCH*SEQ*EMB];    // (b,n,e)

// ---------------------------------------------------------------------------
// tf32 helpers
// ---------------------------------------------------------------------------
__device__ __forceinline__ unsigned f2tf(float f) {
    unsigned u; asm("cvt.rna.tf32.f32 %0, %1;" : "=r"(u) : "f"(f)); return u;
}
__device__ __forceinline__ float tfbits(float f) {
    return __uint_as_float(f2tf(f));
}
__device__ __forceinline__ void mma8(float* c, const unsigned* a, const unsigned* b) {
    asm volatile(
        "mma.sync.aligned.m16n8k8.row.col.f32.tf32.tf32.f32 "
        "{%0,%1,%2,%3}, {%4,%5,%6,%7}, {%8,%9}, {%0,%1,%2,%3};"
        : "+f"(c[0]), "+f"(c[1]), "+f"(c[2]), "+f"(c[3])
        : "r"(a[0]), "r"(a[1]), "r"(a[2]), "r"(a[3]), "r"(b[0]), "r"(b[1]));
}
#define U(x) __float_as_uint(x)

// Fragment-native smem layout:
//   tile X[row][16] per k16 chunk; logical col c16 stored at
//   pos = ((c16&3) ^ ((row>>2)&3))*4 + (c16>>2)
// LDS.128 at quad q = (c4 ^ (row>>2))&3 yields cols {c4,c4+4,c4+8,c4+12}.

// ---------------------------------------------------------------------------
// GEMM core (256 threads): C[m,e] = sum_k A[m,k] * W[e,k].
// CTA tile 64x128, BK=16, 8 warps in 2x4 grid, warp tile 32x32.
// Double-buffered smem (2 x 12KB), ONE __syncthreads per k16 iteration,
// next-chunk LDG prefetch overlapping compute. Store/load fragment patterns
// IDENTICAL to the R6 512-thread kernel; only the tile shape changed so that
// regs*threads fits 2 CTAs/SM (the single barrier no longer idles the SM).
// ---------------------------------------------------------------------------
__device__ __forceinline__ void gemm_core256(const float* __restrict__ Ap,
                                             const float* __restrict__ W,
                                             float* sm,      // [2][3072]
                                             int m0, int e0,
                                             float acc[2][4][4])
{
    const int tid  = threadIdx.x;
    const int lane = tid & 31;
    const int r4 = lane >> 2, c4 = lane & 3;
    const int wid = tid >> 5;
    const int wy = wid >> 2, wx = wid & 3;   // wy 0..1, wx 0..3
    const int rkA  = (r4 >> 2) & 3;          // 0 or 1

    // A loader: 64 rows x 16 cols, 1 float4 per thread
    const int rowA = tid >> 2;               // 0..63
    const int kOfA = (tid & 3) * 4;          // 0,4,8,12
    const int tSA  = kOfA >> 2;              // 0..3
    const int rkstA = (rowA >> 2) & 3;

    // W loader: 128 rows x 16 cols, 2 float4 per thread
    const int rowW = tid >> 1;               // 0..127
    const int kOfW = (tid & 1) * 8;          // 0 or 8
    const int tSW  = kOfW >> 2;              // 0 or 2
    const int rkstW = (rowW >> 2) & 3;

    const float* aP = &Ap[(size_t)(m0 + rowA) * EMB + kOfA];
    const float* wP = &W [(size_t)(e0 + rowW) * EMB + kOfW];

    float4 a0 = *(const float4*)aP;
    float4 w0 = *(const float4*)wP;
    float4 w1 = *(const float4*)(wP + 4);

    const int aE0 = ((0 ^ rkstA) & 3) << 2, aE1 = ((1 ^ rkstA) & 3) << 2;
    const int aE2 = ((2 ^ rkstA) & 3) << 2, aE3 = ((3 ^ rkstA) & 3) << 2;
    const int wE0 = ((0 ^ rkstW) & 3) << 2, wE1 = ((1 ^ rkstW) & 3) << 2;
    const int wE2 = ((2 ^ rkstW) & 3) << 2, wE3 = ((3 ^ rkstW) & 3) << 2;

    #pragma unroll 4
    for (int it = 0; it < 32; ++it) {        // k0 = it*16
        float* stg = sm + (it & 1) * 3072;
        {
            float* ad = stg + (rowA << 4) + tSA;
            ad[aE0] = tfbits(a0.x);
            ad[aE1] = tfbits(a0.y);
            ad[aE2] = tfbits(a0.z);
            ad[aE3] = tfbits(a0.w);
            float* wd = stg + 1024 + (rowW << 4) + tSW;
            wd[wE0    ] = tfbits(w0.x);
            wd[wE1    ] = tfbits(w0.y);
            wd[wE2    ] = tfbits(w0.z);
            wd[wE3    ] = tfbits(w0.w);
            wd[wE0 + 1] = tfbits(w1.x);
            wd[wE1 + 1] = tfbits(w1.y);
            wd[wE2 + 1] = tfbits(w1.z);
            wd[wE3 + 1] = tfbits(w1.w);
        }
        __syncthreads();                     // single barrier per iteration

        // prefetch next chunk (overlaps with compute below)
        if (it < 31) {
            a0 = *(const float4*)(aP + (it + 1) * 16);
            w0 = *(const float4*)(wP + (it + 1) * 16);
            w1 = *(const float4*)(wP + (it + 1) * 16 + 4);
        }

        const float* As_ = stg;              // 64 x 16
        const float* Ws_ = stg + 1024;       // 128 x 16
        float4 alo[2], ahi[2], bv[4];
        #pragma unroll
        for (int mi = 0; mi < 2; mi++) {
            int r = wy * 32 + mi * 16 + r4;
            alo[mi] = *(const float4*)&As_[(r << 4)       + (((c4 ^ rkA)     & 3) << 2)];
            ahi[mi] = *(const float4*)&As_[((r + 8) << 4) + (((c4 ^ rkA ^ 2) & 3) << 2)];
        }
        #pragma unroll
        for (int ni = 0; ni < 4; ni++) {
            int n = wx * 32 + ni * 8 + r4;
            int rkB = (2 * ni + rkA) & 3;
            bv[ni] = *(const float4*)&Ws_[(n << 4) + (((c4 ^ rkB) & 3) << 2)];
        }
        #pragma unroll
        for (int mi = 0; mi < 2; mi++) {
            unsigned a0v[4] = {U(alo[mi].x), U(ahi[mi].x), U(alo[mi].y), U(ahi[mi].y)};
            unsigned a1v[4] = {U(alo[mi].z), U(ahi[mi].z), U(alo[mi].w), U(ahi[mi].w)};
            #pragma unroll
            for (int ni = 0; ni < 4; ni++) {
                unsigned b0v[2] = {U(bv[ni].x), U(bv[ni].y)};
                unsigned b1v[2] = {U(bv[ni].z), U(bv[ni].w)};
                mma8(acc[mi][ni], a0v, b0v);
                mma8(acc[mi][ni], a1v, b1v);
            }
        }
    }
}

// QKV fused projection: z selects WQ/WK/WV, scatter to (b,h,n,d)
__global__ __launch_bounds__(256, 2) void gemm_qkv(const float* __restrict__ x,
                                                   const float* __restrict__ WQ,
                                                   const float* __restrict__ WK,
                                                   const float* __restrict__ WV)
{
    __shared__ float sm[6144];           // 2 stages x (As 1024 + Ws 2048)
    const int z = blockIdx.z;
    const float* W = (z == 0) ? WQ : ((z == 1) ? WK : WV);
    float* dst = (z == 0) ? g_Q : ((z == 1) ? g_K : g_V);

    const int m0 = blockIdx.y * 64;
    const int e0 = blockIdx.x * 128;
    float acc[2][4][4] = {};
    gemm_core256(x, W, sm, m0, e0, acc);

    const int tid = threadIdx.x, lane = tid & 31, wid = tid >> 5;
    const int wy = wid >> 2, wx = wid & 3, r4 = lane >> 2, c4 = lane & 3;
    #pragma unroll
    for (int mi = 0; mi < 2; mi++) {
        #pragma unroll
        for (int ni = 0; ni < 4; ni++) {
            int mlo = m0 + wy * 32 + mi * 16 + r4;
            int e   = e0 + wx * 32 + ni * 8 + c4 * 2;
            int h = e >> 6, d = e & 63;
            int b0 = mlo >> 11, n0 = mlo & (SEQ - 1);
            *(float2*)&dst[((size_t)(b0 * NH + h) * SEQ + n0) * HD + d] =
                make_float2(acc[mi][ni][0], acc[mi][ni][1]);
            int m2 = mlo + 8;
            int b1 = m2 >> 11, n1 = m2 & (SEQ - 1);
            *(float2*)&dst[((size_t)(b1 * NH + h) * SEQ + n1) * HD + d] =
                make_float2(acc[mi][ni][2], acc[mi][ni][3]);
        }
    }
}

// Output projection: A = g_AO, row-major output
__global__ __launch_bounds__(256, 2) void gemm_out(const float* __restrict__ WO,
                                                   float* __restrict__ dout)
{
    __shared__ float sm[6144];
    const int m0 = blockIdx.y * 64;
    const int e0 = blockIdx.x * 128;
    float acc[2][4][4] = {};
    gemm_core256(g_AO, WO, sm, m0, e0, acc);

    const int tid = threadIdx.x, lane = tid & 31, wid = tid >> 5;
    const int wy = wid >> 2, wx = wid & 3, r4 = lane >> 2, c4 = lane & 3;
    #pragma unroll
    for (int mi = 0; mi < 2; mi++) {
        #pragma unroll
        for (int ni = 0; ni < 4; ni++) {
            int mlo = m0 + wy * 32 + mi * 16 + r4;
            int e   = e0 + wx * 32 + ni * 8 + c4 * 2;
            *(float2*)&dout[(size_t)mlo * EMB + e] =
                make_float2(acc[mi][ni][0], acc[mi][ni][1]);
            *(float2*)&dout[(size_t)(mlo + 8) * EMB + e] =
                make_float2(acc[mi][ni][2], acc[mi][ni][3]);
        }
    }
}

// ---------------------------------------------------------------------------
// Causal flash attention — VERBATIM the 385.9us best (R6). Untouched.
// CTA = (b,h) x 128 q-rows. 8 warps x 16 rows. 2 CTAs/SM.
// ---------------------------------------------------------------------------
__global__ __launch_bounds__(256, 2) void attn_tc()
{
    extern __shared__ float smx[];
    float* Qs = smx;                 // 8192
    float* Ks = smx + 8192;          // 4096
    float* Vt = smx + 12288;         // 4096
    float* Ps = smx + 16384;         // 8192

    const int bh = blockIdx.x;                      // 0..31
    const int qt = (int)(gridDim.y - 1 - blockIdx.y); // largest tiles first
    const int q0 = qt * 128;
    const int tid  = threadIdx.x;
    const int lane = tid & 31;
    const int wid  = tid >> 5;
    const int r4 = lane >> 2;
    const int c4 = lane & 3;
    const int rk4 = (r4 >> 2) & 3;   // 0 or 1

    const float* Qg = g_Q + (size_t)bh * SEQ * HD;
    const float* Kg = g_K + (size_t)bh * SEQ * HD;
    const float* Vg = g_V + (size_t)bh * SEQ * HD;

    // load Q tile into fragment-native layout (prescale by 0.125)
    #pragma unroll
    for (int i = 0; i < 8; i++) {
        int idx = tid + i * 256;             // 2048 float4 units
        int r = idx >> 4, d4 = (idx & 15) * 4;
        float4 v = *(const float4*)&Qg[(size_t)(q0 + r) * HD + d4];
        int kc = d4 >> 4, t = (d4 & 15) >> 2;
        int rk = ((r >> 2) ^ kc) & 3;
        float* qd = &Qs[(((kc << 7) + r) << 4) + t];
        qd[((0^rk)<<2)] = tfbits(v.x * 0.125f);
        qd[((1^rk)<<2)] = tfbits(v.y * 0.125f);
        qd[((2^rk)<<2)] = tfbits(v.z * 0.125f);
        qd[((3^rk)<<2)] = tfbits(v.w * 0.125f);
    }

    float m0r = -1e30f, m1r = -1e30f;
    float l0r = 0.0f,  l1r = 0.0f;
    float o[8][4] = {};
    float* Pp = Ps + wid * 1024;

    const int ktiles = (q0 >> 6) + 2;
    const int maskStart = ktiles - 2;

    for (int kt = 0; kt < ktiles; kt++) {
        const int k0 = kt * 64;
        __syncthreads();                      // previous compute done reading K/V
        #pragma unroll
        for (int i = 0; i < 4; i++) {
            int idx = tid + i * 256;          // 1024 float4 units
            int c = idx >> 4, d4 = (idx & 15) * 4;
            float4 kv = *(const float4*)&Kg[(size_t)(k0 + c) * HD + d4];
            int kc = d4 >> 4, t = (d4 & 15) >> 2;
            int rkK = (((c >> 2) ^ kc)) & 3;
            float* kd = &Ks[(((kc << 6) + c) << 4) + t];
            kd[((0^rkK)<<2)] = tfbits(kv.x);
            kd[((1^rkK)<<2)] = tfbits(kv.y);
            kd[((2^rkK)<<2)] = tfbits(kv.z);
            kd[((3^rkK)<<2)] = tfbits(kv.w);
            float4 vv = *(const float4*)&Vg[(size_t)(k0 + c) * HD + d4];
            int kcv = c >> 4, tv = (c & 15) >> 2;
            int qv = ((c & 3) ^ ((d4 >> 2) & 3) ^ kcv) & 3;
            float* vd = &Vt[(((kcv << 6) + d4) << 4) + (qv << 2) + tv];
            vd[0]  = tfbits(vv.x);
            vd[16] = tfbits(vv.y);
            vd[32] = tfbits(vv.z);
            vd[48] = tfbits(vv.w);
        }
        __syncthreads();

        // S = Q K^T : warp computes 16x64
        float s[8][4] = {};
        #pragma unroll
        for (int kc = 0; kc < 4; kc++) {
            int rkQ = (rk4 ^ kc) & 3;
            int qr = (kc << 7) + wid * 16 + r4;
            float4 qlo = *(const float4*)&Qs[(qr << 4)       + (((c4 ^ rkQ)     & 3) << 2)];
            float4 qhi = *(const float4*)&Qs[((qr + 8) << 4) + (((c4 ^ rkQ ^ 2) & 3) << 2)];
            unsigned a0v[4] = {U(qlo.x), U(qhi.x), U(qlo.y), U(qhi.y)};
            unsigned a1v[4] = {U(qlo.z), U(qhi.z), U(qlo.w), U(qhi.w)};
            #pragma unroll
            for (int ni = 0; ni < 8; ni++) {
                int n = ni * 8 + r4;
                int rkB = ((2 * ni + rk4) ^ kc) & 3;
                float4 bv = *(const float4*)&Ks[(((kc << 6) + n) << 4) + (((c4 ^ rkB) & 3) << 2)];
                unsigned b0v[2] = {U(bv.x), U(bv.y)};
                unsigned b1v[2] = {U(bv.z), U(bv.w)};
                mma8(s[ni], a0v, b0v);
                mma8(s[ni], a1v, b1v);
            }
        }

        // causal mask
        if (kt >= maskStart) {
            int grow = q0 + wid * 16 + r4;
            #pragma unroll
            for (int ni = 0; ni < 8; ni++) {
                int gcol = k0 + ni * 8 + c4 * 2;
                if (gcol     > grow    ) s[ni][0] = -1e30f;
                if (gcol + 1 > grow    ) s[ni][1] = -1e30f;
                if (gcol     > grow + 8) s[ni][2] = -1e30f;
                if (gcol + 1 > grow + 8) s[ni][3] = -1e30f;
            }
        }

        // online softmax (2 rows/thread, quad reduce)
        float mx0 = -1e30f, mx1 = -1e30f;
        #pragma unroll
        for (int ni = 0; ni < 8; ni++) {
            mx0 = fmaxf(mx0, fmaxf(s[ni][0], s[ni][1]));
            mx1 = fmaxf(mx1, fmaxf(s[ni][2], s[ni][3]));
        }
        mx0 = fmaxf(mx0, __shfl_xor_sync(0xffffffffu, mx0, 1));
        mx0 = fmaxf(mx0, __shfl_xor_sync(0xffffffffu, mx0, 2));
        mx1 = fmaxf(mx1, __shfl_xor_sync(0xffffffffu, mx1, 1));
        mx1 = fmaxf(mx1, __shfl_xor_sync(0xffffffffu, mx1, 2));
        float mn0 = fmaxf(m0r, mx0), mn1 = fmaxf(m1r, mx1);
        float al0 = __expf(m0r - mn0), al1 = __expf(m1r - mn1);
        float ls0 = 0.0f, ls1 = 0.0f;
        #pragma unroll
        for (int ni = 0; ni < 8; ni++) {
            s[ni][0] = __expf(s[ni][0] - mn0);
            s[ni][1] = __expf(s[ni][1] - mn0);
            s[ni][2] = __expf(s[ni][2] - mn1);
            s[ni][3] = __expf(s[ni][3] - mn1);
            ls0 += s[ni][0] + s[ni][1];
            ls1 += s[ni][2] + s[ni][3];
        }
        ls0 += __shfl_xor_sync(0xffffffffu, ls0, 1);
        ls0 += __shfl_xor_sync(0xffffffffu, ls0, 2);
        ls1 += __shfl_xor_sync(0xffffffffu, ls1, 1);
        ls1 += __shfl_xor_sync(0xffffffffu, ls1, 2);
        l0r = l0r * al0 + ls0;  m0r = mn0;
        l1r = l1r * al1 + ls1;  m1r = mn1;

        #pragma unroll
        for (int ni = 0; ni < 8; ni++) {
            o[ni][0] *= al0; o[ni][1] *= al0;
            o[ni][2] *= al1; o[ni][3] *= al1;
        }

        // stage P (tf32) fragment-native, per-warp region
        #pragma unroll
        for (int ni = 0; ni < 8; ni++) {
            int kc  = ni >> 1;
            int c16 = ((ni & 1) << 3) + (c4 << 1);
            int tP  = c16 >> 2;
            int ql = ((c16 & 3) ^ rk4 ^ kc) & 3;
            int qh = ql ^ 2;
            float* plo = &Pp[(((kc << 4) + r4) << 4) + tP];
            float* phi = plo + (8 << 4);
            plo[(ql      << 2)] = tfbits(s[ni][0]);
            plo[((ql ^ 1) << 2)] = tfbits(s[ni][1]);
            phi[(qh      << 2)] = tfbits(s[ni][2]);
            phi[((qh ^ 1) << 2)] = tfbits(s[ni][3]);
        }
        __syncwarp();

        // O += P @ V
        #pragma unroll
        for (int kc = 0; kc < 4; kc++) {
            int rkP = (rk4 ^ kc) & 3;
            float4 plo4 = *(const float4*)&Pp[((((kc << 4) + r4    ) << 4)) + (((c4 ^ rkP)     & 3) << 2)];
            float4 phi4 = *(const float4*)&Pp[((((kc << 4) + r4 + 8) << 4)) + (((c4 ^ rkP ^ 2) & 3) << 2)];
            unsigned a0v[4] = {U(plo4.x), U(phi4.x), U(plo4.y), U(phi4.y)};
            unsigned a1v[4] = {U(plo4.z), U(phi4.z), U(plo4.w), U(phi4.w)};
            #pragma unroll
            for (int ni = 0; ni < 8; ni++) {
                int n = ni * 8 + r4;
                int rkV = ((2 * ni + rk4) ^ kc) & 3;
                float4 bv = *(const float4*)&Vt[(((kc << 6) + n) << 4) + (((c4 ^ rkV) & 3) << 2)];
                unsigned b0v[2] = {U(bv.x), U(bv.y)};
                unsigned b1v[2] = {U(bv.z), U(bv.w)};
                mma8(o[ni], a0v, b0v);
                mma8(o[ni], a1v, b1v);
            }
        }
        __syncwarp();
    }

    // epilogue: divide by l, write to g_AO (b, n, h*64+d)
    float inv0 = 1.0f / l0r, inv1 = 1.0f / l1r;
    const int b = bh >> 3, h = bh & 7;
    const int row0 = q0 + wid * 16 + r4;
    #pragma unroll
    for (int ni = 0; ni < 8; ni++) {
        int e = h * 64 + ni * 8 + c4 * 2;
        *(float2*)&g_AO[(size_t)(b * SEQ + row0    ) * EMB + e] =
            make_float2(o[ni][0] * inv0, o[ni][1] * inv0);
        *(float2*)&g_AO[(size_t)(b * SEQ + row0 + 8) * EMB + e] =
            make_float2(o[ni][2] * inv1, o[ni][3] * inv1);
    }
}

// ---------------------------------------------------------------------------

extern "C" void kernel_launch(void* const* d_in, const int* in_sizes, int n_in,
                              void* d_out, int out_size)
{
    const float* x  = (const float*)d_in[0];
    const float* WQ = (const float*)d_in[1];
    const float* WK = (const float*)d_in[2];
    const float* WV = (const float*)d_in[3];
    const float* WO = (const float*)d_in[4];
    // d_in[5] = mask (tril) — causal, applied analytically in-kernel.
    float* out = (float*)d_out;

    const int SMEM_ATTN = 24576 * (int)sizeof(float);   // 96KB
    static bool attr_set = false;
    if (!attr_set) {
        cudaFuncSetAttribute(attn_tc,
                             cudaFuncAttributeMaxDynamicSharedMemorySize, SMEM_ATTN);
        attr_set = true;
    }

    gemm_qkv<<<dim3(EMB / 128, MROWS / 64, 3), 256>>>(x, WQ, WK, WV);

    attn_tc<<<dim3(BATCH * NH, SEQ / 128), 256, SMEM_ATTN>>>();

    gemm_out<<<dim3(EMB / 128, MROWS / 64), 256>>>(WO, out);
}

// round 12
// speedup vs baseline: 1.0027x; 1.0027x over previous
#include <cuda_runtime.h>
#include <cstdint>
#include <math.h>

#define BATCH 4
#define SEQ   2048
#define EMB   512
#define NH    8
#define HD    64
#define MROWS (BATCH*SEQ)   // 8192

// Scratch (device globals: allocation-free per harness rules)
__device__ float g_Q[BATCH*NH*SEQ*HD];   // (b,h,n,d)
__device__ float g_K[BATCH*NH*SEQ*HD];
__device__ float g_V[BATCH*NH*SEQ*HD];
__device__ float g_AO[BATCH*SEQ*EMB];    // (b,n,e)

// ---------------------------------------------------------------------------
// tf32 helpers
// ---------------------------------------------------------------------------
__device__ __forceinline__ unsigned f2tf(float f) {
    unsigned u; asm("cvt.rna.tf32.f32 %0, %1;" : "=r"(u) : "f"(f)); return u;
}
__device__ __forceinline__ float tfbits(float f) {
    return __uint_as_float(f2tf(f));
}
__device__ __forceinline__ void mma8(float* c, const unsigned* a, const unsigned* b) {
    asm volatile(
        "mma.sync.aligned.m16n8k8.row.col.f32.tf32.tf32.f32 "
        "{%0,%1,%2,%3}, {%4,%5,%6,%7}, {%8,%9}, {%0,%1,%2,%3};"
        : "+f"(c[0]), "+f"(c[1]), "+f"(c[2]), "+f"(c[3])
        : "r"(a[0]), "r"(a[1]), "r"(a[2]), "r"(a[3]), "r"(b[0]), "r"(b[1]));
}
#define U(x) __float_as_uint(x)

// Fragment-native smem layout:
//   tile X[row][16] per k16 chunk; logical col c16 stored at
//   pos = ((c16&3) ^ ((row>>2)&3))*4 + (c16>>2)
// LDS.128 at quad q = (c4 ^ (row>>2))&3 yields cols {c4,c4+4,c4+8,c4+12}.

// ---------------------------------------------------------------------------
// GEMM core (256 threads): C[m,e] = sum_k A[m,k] * W[e,k].
// CTA tile 64x128, BK=16, 8 warps in 2x4 grid, warp tile 32x32.
// Double-buffered smem (2 x 12KB), ONE __syncthreads per k16 iteration,
// next-chunk LDG prefetch overlapping compute. Store/load fragment patterns
// IDENTICAL to the R6 512-thread kernel; only the tile shape changed so that
// regs*threads fits 2 CTAs/SM (the single barrier no longer idles the SM).
// ---------------------------------------------------------------------------
__device__ __forceinline__ void gemm_core256(const float* __restrict__ Ap,
                                             const float* __restrict__ W,
                                             float* sm,      // [2][3072]
                                             int m0, int e0,
                                             float acc[2][4][4])
{
    const int tid  = threadIdx.x;
    const int lane = tid & 31;
    const int r4 = lane >> 2, c4 = lane & 3;
    const int wid = tid >> 5;
    const int wy = wid >> 2, wx = wid & 3;   // wy 0..1, wx 0..3
    const int rkA  = (r4 >> 2) & 3;          // 0 or 1

    // A loader: 64 rows x 16 cols, 1 float4 per thread
    const int rowA = tid >> 2;               // 0..63
    const int kOfA = (tid & 3) * 4;          // 0,4,8,12
    const int tSA  = kOfA >> 2;              // 0..3
    const int rkstA = (rowA >> 2) & 3;

    // W loader: 128 rows x 16 cols, 2 float4 per thread
    const int rowW = tid >> 1;               // 0..127
    const int kOfW = (tid & 1) * 8;          // 0 or 8
    const int tSW  = kOfW >> 2;              // 0 or 2
    const int rkstW = (rowW >> 2) & 3;

    const float* aP = &Ap[(size_t)(m0 + rowA) * EMB + kOfA];
    const float* wP = &W [(size_t)(e0 + rowW) * EMB + kOfW];

    float4 a0 = *(const float4*)aP;
    float4 w0 = *(const float4*)wP;
    float4 w1 = *(const float4*)(wP + 4);

    const int aE0 = ((0 ^ rkstA) & 3) << 2, aE1 = ((1 ^ rkstA) & 3) << 2;
    const int aE2 = ((2 ^ rkstA) & 3) << 2, aE3 = ((3 ^ rkstA) & 3) << 2;
    const int wE0 = ((0 ^ rkstW) & 3) << 2, wE1 = ((1 ^ rkstW) & 3) << 2;
    const int wE2 = ((2 ^ rkstW) & 3) << 2, wE3 = ((3 ^ rkstW) & 3) << 2;

    #pragma unroll 4
    for (int it = 0; it < 32; ++it) {        // k0 = it*16
        float* stg = sm + (it & 1) * 3072;
        {
            float* ad = stg + (rowA << 4) + tSA;
            ad[aE0] = tfbits(a0.x);
            ad[aE1] = tfbits(a0.y);
            ad[aE2] = tfbits(a0.z);
            ad[aE3] = tfbits(a0.w);
            float* wd = stg + 1024 + (rowW << 4) + tSW;
            wd[wE0    ] = tfbits(w0.x);
            wd[wE1    ] = tfbits(w0.y);
            wd[wE2    ] = tfbits(w0.z);
            wd[wE3    ] = tfbits(w0.w);
            wd[wE0 + 1] = tfbits(w1.x);
            wd[wE1 + 1] = tfbits(w1.y);
            wd[wE2 + 1] = tfbits(w1.z);
            wd[wE3 + 1] = tfbits(w1.w);
        }
        __syncthreads();                     // single barrier per iteration

        // prefetch next chunk (overlaps with compute below)
        if (it < 31) {
            a0 = *(const float4*)(aP + (it + 1) * 16);
            w0 = *(const float4*)(wP + (it + 1) * 16);
            w1 = *(const float4*)(wP + (it + 1) * 16 + 4);
        }

        const float* As_ = stg;              // 64 x 16
        const float* Ws_ = stg + 1024;       // 128 x 16
        float4 alo[2], ahi[2], bv[4];
        #pragma unroll
        for (int mi = 0; mi < 2; mi++) {
            int r = wy * 32 + mi * 16 + r4;
            alo[mi] = *(const float4*)&As_[(r << 4)       + (((c4 ^ rkA)     & 3) << 2)];
            ahi[mi] = *(const float4*)&As_[((r + 8) << 4) + (((c4 ^ rkA ^ 2) & 3) << 2)];
        }
        #pragma unroll
        for (int ni = 0; ni < 4; ni++) {
            int n = wx * 32 + ni * 8 + r4;
            int rkB = (2 * ni + rkA) & 3;
            bv[ni] = *(const float4*)&Ws_[(n << 4) + (((c4 ^ rkB) & 3) << 2)];
        }
        #pragma unroll
        for (int mi = 0; mi < 2; mi++) {
            unsigned a0v[4] = {U(alo[mi].x), U(ahi[mi].x), U(alo[mi].y), U(ahi[mi].y)};
            unsigned a1v[4] = {U(alo[mi].z), U(ahi[mi].z), U(alo[mi].w), U(ahi[mi].w)};
            #pragma unroll
            for (int ni = 0; ni < 4; ni++) {
                unsigned b0v[2] = {U(bv[ni].x), U(bv[ni].y)};
                unsigned b1v[2] = {U(bv[ni].z), U(bv[ni].w)};
                mma8(acc[mi][ni], a0v, b0v);
                mma8(acc[mi][ni], a1v, b1v);
            }
        }
    }
}

// QKV fused projection: z selects WQ/WK/WV, scatter to (b,h,n,d)
__global__ __launch_bounds__(256, 2) void gemm_qkv(const float* __restrict__ x,
                                                   const float* __restrict__ WQ,
                                                   const float* __restrict__ WK,
                                                   const float* __restrict__ WV)
{
    __shared__ float sm[6144];           // 2 stages x (As 1024 + Ws 2048)
    const int z = blockIdx.z;
    const float* W = (z == 0) ? WQ : ((z == 1) ? WK : WV);
    float* dst = (z == 0) ? g_Q : ((z == 1) ? g_K : g_V);

    const int m0 = blockIdx.y * 64;
    const int e0 = blockIdx.x * 128;
    float acc[2][4][4] = {};
    gemm_core256(x, W, sm, m0, e0, acc);

    const int tid = threadIdx.x, lane = tid & 31, wid = tid >> 5;
    const int wy = wid >> 2, wx = wid & 3, r4 = lane >> 2, c4 = lane & 3;
    #pragma unroll
    for (int mi = 0; mi < 2; mi++) {
        #pragma unroll
        for (int ni = 0; ni < 4; ni++) {
            int mlo = m0 + wy * 32 + mi * 16 + r4;
            int e   = e0 + wx * 32 + ni * 8 + c4 * 2;
            int h = e >> 6, d = e & 63;
            int b0 = mlo >> 11, n0 = mlo & (SEQ - 1);
            *(float2*)&dst[((size_t)(b0 * NH + h) * SEQ + n0) * HD + d] =
                make_float2(acc[mi][ni][0], acc[mi][ni][1]);
            int m2 = mlo + 8;
            int b1 = m2 >> 11, n1 = m2 & (SEQ - 1);
            *(float2*)&dst[((size_t)(b1 * NH + h) * SEQ + n1) * HD + d] =
                make_float2(acc[mi][ni][2], acc[mi][ni][3]);
        }
    }
}

// Output projection: A = g_AO, row-major output
__global__ __launch_bounds__(256, 2) void gemm_out(const float* __restrict__ WO,
                                                   float* __restrict__ dout)
{
    __shared__ float sm[6144];
    const int m0 = blockIdx.y * 64;
    const int e0 = blockIdx.x * 128;
    float acc[2][4][4] = {};
    gemm_core256(g_AO, WO, sm, m0, e0, acc);

    const int tid = threadIdx.x, lane = tid & 31, wid = tid >> 5;
    const int wy = wid >> 2, wx = wid & 3, r4 = lane >> 2, c4 = lane & 3;
    #pragma unroll
    for (int mi = 0; mi < 2; mi++) {
        #pragma unroll
        for (int ni = 0; ni < 4; ni++) {
            int mlo = m0 + wy * 32 + mi * 16 + r4;
            int e   = e0 + wx * 32 + ni * 8 + c4 * 2;
            *(float2*)&dout[(size_t)mlo * EMB + e] =
                make_float2(acc[mi][ni][0], acc[mi][ni][1]);
            *(float2*)&dout[(size_t)(mlo + 8) * EMB + e] =
                make_float2(acc[mi][ni][2], acc[mi][ni][3]);
        }
    }
}

// ---------------------------------------------------------------------------
// Causal flash attention — VERBATIM the 385.9us best (R6). Untouched.
// CTA = (b,h) x 128 q-rows. 8 warps x 16 rows. 2 CTAs/SM.
// ---------------------------------------------------------------------------
__global__ __launch_bounds__(256, 2) void attn_tc()
{
    extern __shared__ float smx[];
    float* Qs = smx;                 // 8192
    float* Ks = smx + 8192;          // 4096
    float* Vt = smx + 12288;         // 4096
    float* Ps = smx + 16384;         // 8192

    const int bh = blockIdx.x;                      // 0..31
    const int qt = (int)(gridDim.y - 1 - blockIdx.y); // largest tiles first
    const int q0 = qt * 128;
    const int tid  = threadIdx.x;
    const int lane = tid & 31;
    const int wid  = tid >> 5;
    const int r4 = lane >> 2;
    const int c4 = lane & 3;
    const int rk4 = (r4 >> 2) & 3;   // 0 or 1

    const float* Qg = g_Q + (size_t)bh * SEQ * HD;
    const float* Kg = g_K + (size_t)bh * SEQ * HD;
    const float* Vg = g_V + (size_t)bh * SEQ * HD;

    // load Q tile into fragment-native layout (prescale by 0.125)
    #pragma unroll
    for (int i = 0; i < 8; i++) {
        int idx = tid + i * 256;             // 2048 float4 units
        int r = idx >> 4, d4 = (idx & 15) * 4;
        float4 v = *(const float4*)&Qg[(size_t)(q0 + r) * HD + d4];
        int kc = d4 >> 4, t = (d4 & 15) >> 2;
        int rk = ((r >> 2) ^ kc) & 3;
        float* qd = &Qs[(((kc << 7) + r) << 4) + t];
        qd[((0^rk)<<2)] = tfbits(v.x * 0.125f);
        qd[((1^rk)<<2)] = tfbits(v.y * 0.125f);
        qd[((2^rk)<<2)] = tfbits(v.z * 0.125f);
        qd[((3^rk)<<2)] = tfbits(v.w * 0.125f);
    }

    float m0r = -1e30f, m1r = -1e30f;
    float l0r = 0.0f,  l1r = 0.0f;
    float o[8][4] = {};
    float* Pp = Ps + wid * 1024;

    const int ktiles = (q0 >> 6) + 2;
    const int maskStart = ktiles - 2;

    for (int kt = 0; kt < ktiles; kt++) {
        const int k0 = kt * 64;
        __syncthreads();                      // previous compute done reading K/V
        #pragma unroll
        for (int i = 0; i < 4; i++) {
            int idx = tid + i * 256;          // 1024 float4 units
            int c = idx >> 4, d4 = (idx & 15) * 4;
            float4 kv = *(const float4*)&Kg[(size_t)(k0 + c) * HD + d4];
            int kc = d4 >> 4, t = (d4 & 15) >> 2;
            int rkK = (((c >> 2) ^ kc)) & 3;
            float* kd = &Ks[(((kc << 6) + c) << 4) + t];
            kd[((0^rkK)<<2)] = tfbits(kv.x);
            kd[((1^rkK)<<2)] = tfbits(kv.y);
            kd[((2^rkK)<<2)] = tfbits(kv.z);
            kd[((3^rkK)<<2)] = tfbits(kv.w);
            float4 vv = *(const float4*)&Vg[(size_t)(k0 + c) * HD + d4];
            int kcv = c >> 4, tv = (c & 15) >> 2;
            int qv = ((c & 3) ^ ((d4 >> 2) & 3) ^ kcv) & 3;
            float* vd = &Vt[(((kcv << 6) + d4) << 4) + (qv << 2) + tv];
            vd[0]  = tfbits(vv.x);
            vd[16] = tfbits(vv.y);
            vd[32] = tfbits(vv.z);
            vd[48] = tfbits(vv.w);
        }
        __syncthreads();

        // S = Q K^T : warp computes 16x64
        float s[8][4] = {};
        #pragma unroll
        for (int kc = 0; kc < 4; kc++) {
            int rkQ = (rk4 ^ kc) & 3;
            int qr = (kc << 7) + wid * 16 + r4;
            float4 qlo = *(const float4*)&Qs[(qr << 4)       + (((c4 ^ rkQ)     & 3) << 2)];
            float4 qhi = *(const float4*)&Qs[((qr + 8) << 4) + (((c4 ^ rkQ ^ 2) & 3) << 2)];
            unsigned a0v[4] = {U(qlo.x), U(qhi.x), U(qlo.y), U(qhi.y)};
            unsigned a1v[4] = {U(qlo.z), U(qhi.z), U(qlo.w), U(qhi.w)};
            #pragma unroll
            for (int ni = 0; ni < 8; ni++) {
                int n = ni * 8 + r4;
                int rkB = ((2 * ni + rk4) ^ kc) & 3;
                float4 bv = *(const float4*)&Ks[(((kc << 6) + n) << 4) + (((c4 ^ rkB) & 3) << 2)];
                unsigned b0v[2] = {U(bv.x), U(bv.y)};
                unsigned b1v[2] = {U(bv.z), U(bv.w)};
                mma8(s[ni], a0v, b0v);
                mma8(s[ni], a1v, b1v);
            }
        }

        // causal mask
        if (kt >= maskStart) {
            int grow = q0 + wid * 16 + r4;
            #pragma unroll
            for (int ni = 0; ni < 8; ni++) {
                int gcol = k0 + ni * 8 + c4 * 2;
                if (gcol     > grow    ) s[ni][0] = -1e30f;
                if (gcol + 1 > grow    ) s[ni][1] = -1e30f;
                if (gcol     > grow + 8) s[ni][2] = -1e30f;
                if (gcol + 1 > grow + 8) s[ni][3] = -1e30f;
            }
        }

        // online softmax (2 rows/thread, quad reduce)
        float mx0 = -1e30f, mx1 = -1e30f;
        #pragma unroll
        for (int ni = 0; ni < 8; ni++) {
            mx0 = fmaxf(mx0, fmaxf(s[ni][0], s[ni][1]));
            mx1 = fmaxf(mx1, fmaxf(s[ni][2], s[ni][3]));
        }
        mx0 = fmaxf(mx0, __shfl_xor_sync(0xffffffffu, mx0, 1));
        mx0 = fmaxf(mx0, __shfl_xor_sync(0xffffffffu, mx0, 2));
        mx1 = fmaxf(mx1, __shfl_xor_sync(0xffffffffu, mx1, 1));
        mx1 = fmaxf(mx1, __shfl_xor_sync(0xffffffffu, mx1, 2));
        float mn0 = fmaxf(m0r, mx0), mn1 = fmaxf(m1r, mx1);
        float al0 = __expf(m0r - mn0), al1 = __expf(m1r - mn1);
        float ls0 = 0.0f, ls1 = 0.0f;
        #pragma unroll
        for (int ni = 0; ni < 8; ni++) {
            s[ni][0] = __expf(s[ni][0] - mn0);
            s[ni][1] = __expf(s[ni][1] - mn0);
            s[ni][2] = __expf(s[ni][2] - mn1);
            s[ni][3] = __expf(s[ni][3] - mn1);
            ls0 += s[ni][0] + s[ni][1];
            ls1 += s[ni][2] + s[ni][3];
        }
        ls0 += __shfl_xor_sync(0xffffffffu, ls0, 1);
        ls0 += __shfl_xor_sync(0xffffffffu, ls0, 2);
        ls1 += __shfl_xor_sync(0xffffffffu, ls1, 1);
        ls1 += __shfl_xor_sync(0xffffffffu, ls1, 2);
        l0r = l0r * al0 + ls0;  m0r = mn0;
        l1r = l1r * al1 + ls1;  m1r = mn1;

        #pragma unroll
        for (int ni = 0; ni < 8; ni++) {
            o[ni][0] *= al0; o[ni][1] *= al0;
            o[ni][2] *= al1; o[ni][3] *= al1;
        }

        // stage P (tf32) fragment-native, per-warp region
        #pragma unroll
        for (int ni = 0; ni < 8; ni++) {
            int kc  = ni >> 1;
            int c16 = ((ni & 1) << 3) + (c4 << 1);
            int tP  = c16 >> 2;
            int ql = ((c16 & 3) ^ rk4 ^ kc) & 3;
            int qh = ql ^ 2;
            float* plo = &Pp[(((kc << 4) + r4) << 4) + tP];
            float* phi = plo + (8 << 4);
            plo[(ql      << 2)] = tfbits(s[ni][0]);
            plo[((ql ^ 1) << 2)] = tfbits(s[ni][1]);
            phi[(qh      << 2)] = tfbits(s[ni][2]);
            phi[((qh ^ 1) << 2)] = tfbits(s[ni][3]);
        }
        __syncwarp();

        // O += P @ V
        #pragma unroll
        for (int kc = 0; kc < 4; kc++) {
            int rkP = (rk4 ^ kc) & 3;
            float4 plo4 = *(const float4*)&Pp[((((kc << 4) + r4    ) << 4)) + (((c4 ^ rkP)     & 3) << 2)];
            float4 phi4 = *(const float4*)&Pp[((((kc << 4) + r4 + 8) << 4)) + (((c4 ^ rkP ^ 2) & 3) << 2)];
            unsigned a0v[4] = {U(plo4.x), U(phi4.x), U(plo4.y), U(phi4.y)};
            unsigned a1v[4] = {U(plo4.z), U(phi4.z), U(plo4.w), U(phi4.w)};
            #pragma unroll
            for (int ni = 0; ni < 8; ni++) {
                int n = ni * 8 + r4;
                int rkV = ((2 * ni + rk4) ^ kc) & 3;
                float4 bv = *(const float4*)&Vt[(((kc << 6) + n) << 4) + (((c4 ^ rkV) & 3) << 2)];
                unsigned b0v[2] = {U(bv.x), U(bv.y)};
                unsigned b1v[2] = {U(bv.z), U(bv.w)};
                mma8(o[ni], a0v, b0v);
                mma8(o[ni], a1v, b1v);
            }
        }
        __syncwarp();
    }

    // epilogue: divide by l, write to g_AO (b, n, h*64+d)
    float inv0 = 1.0f / l0r, inv1 = 1.0f / l1r;
    const int b = bh >> 3, h = bh & 7;
    const int row0 = q0 + wid * 16 + r4;
    #pragma unroll
    for (int ni = 0; ni < 8; ni++) {
        int e = h * 64 + ni * 8 + c4 * 2;
        *(float2*)&g_AO[(size_t)(b * SEQ + row0    ) * EMB + e] =
            make_float2(o[ni][0] * inv0, o[ni][1] * inv0);
        *(float2*)&g_AO[(size_t)(b * SEQ + row0 + 8) * EMB + e] =
            make_float2(o[ni][2] * inv1, o[ni][3] * inv1);
    }
}

// ---------------------------------------------------------------------------

extern "C" void kernel_launch(void* const* d_in, const int* in_sizes, int n_in,
                              void* d_out, int out_size)
{
    const float* x  = (const float*)d_in[0];
    const float* WQ = (const float*)d_in[1];
    const float* WK = (const float*)d_in[2];
    const float* WV = (const float*)d_in[3];
    const float* WO = (const float*)d_in[4];
    // d_in[5] = mask (tril) — causal, applied analytically in-kernel.
    float* out = (float*)d_out;

    const int SMEM_ATTN = 24576 * (int)sizeof(float);   // 96KB
    static bool attr_set = false;
    if (!attr_set) {
        cudaFuncSetAttribute(attn_tc,
                             cudaFuncAttributeMaxDynamicSharedMemorySize, SMEM_ATTN);
        attr_set = true;
    }

    gemm_qkv<<<dim3(EMB / 128, MROWS / 64, 3), 256>>>(x, WQ, WK, WV);

    attn_tc<<<dim3(BATCH * NH, SEQ / 128), 256, SMEM_ATTN>>>();

    gemm_out<<<dim3(EMB / 128, MROWS / 64), 256>>>(WO, out);
}

// round 13
// speedup vs baseline: 1.1023x; 1.0994x over previous
#include <cuda_runtime.h>
#include <cstdint>
#include <math.h>

#define BATCH 4
#define SEQ   2048
#define EMB   512
#define NH    8
#define HD    64
#define MROWS (BATCH*SEQ)   // 8192

// Scratch (device globals: allocation-free per harness rules)
__device__ float g_Q[BATCH*NH*SEQ*HD];   // (b,h,n,d)
__device__ float g_K[BATCH*NH*SEQ*HD];
__device__ float g_V[BATCH*NH*SEQ*HD];
__device__ float g_AO[BATCH*SEQ*EMB];    // (b,n,e)

// ---------------------------------------------------------------------------
// tf32 helpers
// ---------------------------------------------------------------------------
__device__ __forceinline__ unsigned f2tf(float f) {
    unsigned u; asm("cvt.rna.tf32.f32 %0, %1;" : "=r"(u) : "f"(f)); return u;
}
__device__ __forceinline__ float tfbits(float f) {
    return __uint_as_float(f2tf(f));
}
__device__ __forceinline__ void mma8(float* c, const unsigned* a, const unsigned* b) {
    asm volatile(
        "mma.sync.aligned.m16n8k8.row.col.f32.tf32.tf32.f32 "
        "{%0,%1,%2,%3}, {%4,%5,%6,%7}, {%8,%9}, {%0,%1,%2,%3};"
        : "+f"(c[0]), "+f"(c[1]), "+f"(c[2]), "+f"(c[3])
        : "r"(a[0]), "r"(a[1]), "r"(a[2]), "r"(a[3]), "r"(b[0]), "r"(b[1]));
}
#define U(x) __float_as_uint(x)

// Fragment-native smem layout:
//   tile X[row][16] per k16 chunk; logical col c16 stored at
//   pos = ((c16&3) ^ ((row>>2)&3))*4 + (c16>>2)
// LDS.128 at quad q = (c4 ^ (row>>2))&3 yields cols {c4,c4+4,c4+8,c4+12}.

// ---------------------------------------------------------------------------
// GEMM core (512 threads) — VERBATIM R6 (best: 148.5us qkv). Untouched.
// CTA tile 128x128, BK=16, 16 warps in 4x4 grid, warp tile 32x32.
// Double-buffered smem (2 x 16KB), ONE __syncthreads per k16 iteration.
// ---------------------------------------------------------------------------
__device__ __forceinline__ void gemm_core512(const float* __restrict__ Ap,
                                             const float* __restrict__ W,
                                             float* sm,      // [2][4096]
                                             int m0, int e0,
                                             float acc[2][4][4])
{
    const int tid  = threadIdx.x;
    const int lane = tid & 31;
    const int r4 = lane >> 2, c4 = lane & 3;
    const int wid = tid >> 5;
    const int wy = wid >> 2, wx = wid & 3;
    const int rkA  = (r4 >> 2) & 3;      // 0 or 1

    const int rowL = tid >> 2;           // 0..127
    const int kOff = (tid & 3) * 4;      // 0,4,8,12
    const int tS   = kOff >> 2;          // 0..3
    const int rkst = (rowL >> 2) & 3;

    const float* aP = &Ap[(size_t)(m0 + rowL) * EMB + kOff];
    const float* wP = &W [(size_t)(e0 + rowL) * EMB + kOff];

    float4 a0 = *(const float4*)aP;
    float4 w0 = *(const float4*)wP;

    const int e0i = ((0 ^ rkst) & 3) << 2, e1i = ((1 ^ rkst) & 3) << 2;
    const int e2i = ((2 ^ rkst) & 3) << 2, e3i = ((3 ^ rkst) & 3) << 2;

    #pragma unroll 4
    for (int it = 0; it < 32; ++it) {    // k0 = it*16
        float* stg = sm + (it & 1) * 4096;
        {
            float* ad = stg + (rowL << 4) + tS;
            ad[e0i] = tfbits(a0.x);
            ad[e1i] = tfbits(a0.y);
            ad[e2i] = tfbits(a0.z);
            ad[e3i] = tfbits(a0.w);
            float* wd = stg + 2048 + (rowL << 4) + tS;
            wd[e0i] = tfbits(w0.x);
            wd[e1i] = tfbits(w0.y);
            wd[e2i] = tfbits(w0.z);
            wd[e3i] = tfbits(w0.w);
        }
        __syncthreads();                 // single barrier per iteration

        // prefetch next chunk (overlaps with compute below)
        if (it < 31) {
            a0 = *(const float4*)(aP + (it + 1) * 16);
            w0 = *(const float4*)(wP + (it + 1) * 16);
        }

        const float* As_ = stg;
        const float* Ws_ = stg + 2048;
        float4 alo[2], ahi[2], bv[4];
        #pragma unroll
        for (int mi = 0; mi < 2; mi++) {
            int r = wy * 32 + mi * 16 + r4;
            alo[mi] = *(const float4*)&As_[(r << 4)       + (((c4 ^ rkA)     & 3) << 2)];
            ahi[mi] = *(const float4*)&As_[((r + 8) << 4) + (((c4 ^ rkA ^ 2) & 3) << 2)];
        }
        #pragma unroll
        for (int ni = 0; ni < 4; ni++) {
            int n = wx * 32 + ni * 8 + r4;
            int rkB = (2 * ni + rkA) & 3;
            bv[ni] = *(const float4*)&Ws_[(n << 4) + (((c4 ^ rkB) & 3) << 2)];
        }
        #pragma unroll
        for (int mi = 0; mi < 2; mi++) {
            unsigned a0v[4] = {U(alo[mi].x), U(ahi[mi].x), U(alo[mi].y), U(ahi[mi].y)};
            unsigned a1v[4] = {U(alo[mi].z), U(ahi[mi].z), U(alo[mi].w), U(ahi[mi].w)};
            #pragma unroll
            for (int ni = 0; ni < 4; ni++) {
                unsigned b0v[2] = {U(bv[ni].x), U(bv[ni].y)};
                unsigned b1v[2] = {U(bv[ni].z), U(bv[ni].w)};
                mma8(acc[mi][ni], a0v, b0v);
                mma8(acc[mi][ni], a1v, b1v);
            }
        }
    }
}

// QKV fused projection: z selects WQ/WK/WV, scatter to (b,h,n,d)
__global__ __launch_bounds__(512) void gemm_qkv(const float* __restrict__ x,
                                                const float* __restrict__ WQ,
                                                const float* __restrict__ WK,
                                                const float* __restrict__ WV)
{
    __shared__ float sm[8192];           // 2 stages x (As 2048 + Ws 2048)
    const int z = blockIdx.z;
    const float* W = (z == 0) ? WQ : ((z == 1) ? WK : WV);
    float* dst = (z == 0) ? g_Q : ((z == 1) ? g_K : g_V);

    const int m0 = blockIdx.y * 128;
    const int e0 = blockIdx.x * 128;
    float acc[2][4][4] = {};
    gemm_core512(x, W, sm, m0, e0, acc);

    const int tid = threadIdx.x, lane = tid & 31, wid = tid >> 5;
    const int wy = wid >> 2, wx = wid & 3, r4 = lane >> 2, c4 = lane & 3;
    #pragma unroll
    for (int mi = 0; mi < 2; mi++) {
        #pragma unroll
        for (int ni = 0; ni < 4; ni++) {
            int mlo = m0 + wy * 32 + mi * 16 + r4;
            int e   = e0 + wx * 32 + ni * 8 + c4 * 2;
            int h = e >> 6, d = e & 63;
            int b0 = mlo >> 11, n0 = mlo & (SEQ - 1);
            *(float2*)&dst[((size_t)(b0 * NH + h) * SEQ + n0) * HD + d] =
                make_float2(acc[mi][ni][0], acc[mi][ni][1]);
            int m2 = mlo + 8;
            int b1 = m2 >> 11, n1 = m2 & (SEQ - 1);
            *(float2*)&dst[((size_t)(b1 * NH + h) * SEQ + n1) * HD + d] =
                make_float2(acc[mi][ni][2], acc[mi][ni][3]);
        }
    }
}

// Output projection: A = g_AO, row-major output
__global__ __launch_bounds__(512) void gemm_out(const float* __restrict__ WO,
                                                float* __restrict__ dout)
{
    __shared__ float sm[8192];
    const int m0 = blockIdx.y * 128;
    const int e0 = blockIdx.x * 128;
    float acc[2][4][4] = {};
    gemm_core512(g_AO, WO, sm, m0, e0, acc);

    const int tid = threadIdx.x, lane = tid & 31, wid = tid >> 5;
    const int wy = wid >> 2, wx = wid & 3, r4 = lane >> 2, c4 = lane & 3;
    #pragma unroll
    for (int mi = 0; mi < 2; mi++) {
        #pragma unroll
        for (int ni = 0; ni < 4; ni++) {
            int mlo = m0 + wy * 32 + mi * 16 + r4;
            int e   = e0 + wx * 32 + ni * 8 + c4 * 2;
            *(float2*)&dout[(size_t)mlo * EMB + e] =
                make_float2(acc[mi][ni][0], acc[mi][ni][1]);
            *(float2*)&dout[(size_t)(mlo + 8) * EMB + e] =
                make_float2(acc[mi][ni][2], acc[mi][ni][3]);
        }
    }
}

// ---------------------------------------------------------------------------
// Causal flash attention, tf32 mma, fragment-native smem.
// R12 changes vs the 385.9us version:
//   * Q fragments live in REGISTERS (staged once through the Ps region) —
//     frees 32KB smem and 8 LDS.128/ktile.
//   * K/V tiles double-buffered (2 x 16KB each pair) -> ONE __syncthreads
//     per ktile (same single-barrier dbuf argument as the GEMM core).
//   * Softmax / P staging / PV byte-identical to the best version.
// Smem: Ps 32KB | Ks[2] 16+16KB... total 24576 floats = 96KB -> 2 CTAs/SM.
// ---------------------------------------------------------------------------
__global__ __launch_bounds__(256, 2) void attn_tc()
{
    extern __shared__ float smx[];
    float* Ps  = smx;                // 8192 floats (also Q staging at startup)
    float* KsB = smx + 8192;         // 2 x 4096
    float* VtB = smx + 16384;        // 2 x 4096

    const int bh = blockIdx.x;                      // 0..31
    const int qt = (int)(gridDim.y - 1 - blockIdx.y); // largest tiles first
    const int q0 = qt * 128;
    const int tid  = threadIdx.x;
    const int lane = tid & 31;
    const int wid  = tid >> 5;
    const int r4 = lane >> 2;
    const int c4 = lane & 3;
    const int rk4 = (r4 >> 2) & 3;   // 0 or 1

    const float* Qg = g_Q + (size_t)bh * SEQ * HD;
    const float* Kg = g_K + (size_t)bh * SEQ * HD;
    const float* Vg = g_V + (size_t)bh * SEQ * HD;

    // ---- stage Q into Ps region (fragment-native layout, prescale 0.125) ----
    #pragma unroll
    for (int i = 0; i < 8; i++) {
        int idx = tid + i * 256;             // 2048 float4 units
        int r = idx >> 4, d4 = (idx & 15) * 4;
        float4 v = *(const float4*)&Qg[(size_t)(q0 + r) * HD + d4];
        int kc = d4 >> 4, t = (d4 & 15) >> 2;
        int rk = ((r >> 2) ^ kc) & 3;
        float* qd = &Ps[(((kc << 7) + r) << 4) + t];
        qd[((0^rk)<<2)] = tfbits(v.x * 0.125f);
        qd[((1^rk)<<2)] = tfbits(v.y * 0.125f);
        qd[((2^rk)<<2)] = tfbits(v.z * 0.125f);
        qd[((3^rk)<<2)] = tfbits(v.w * 0.125f);
    }
    __syncthreads();

    // ---- extract this warp's Q fragments into registers ----
    unsigned Qr[4][8];
    #pragma unroll
    for (int kc = 0; kc < 4; kc++) {
        int rkQ = (rk4 ^ kc) & 3;
        int qr = (kc << 7) + wid * 16 + r4;
        float4 qlo = *(const float4*)&Ps[(qr << 4)       + (((c4 ^ rkQ)     & 3) << 2)];
        float4 qhi = *(const float4*)&Ps[((qr + 8) << 4) + (((c4 ^ rkQ ^ 2) & 3) << 2)];
        Qr[kc][0] = U(qlo.x); Qr[kc][1] = U(qhi.x);
        Qr[kc][2] = U(qlo.y); Qr[kc][3] = U(qhi.y);
        Qr[kc][4] = U(qlo.z); Qr[kc][5] = U(qhi.z);
        Qr[kc][6] = U(qlo.w); Qr[kc][7] = U(qhi.w);
    }
    __syncthreads();                 // Ps free for P staging from here on

    float m0r = -1e30f, m1r = -1e30f;
    float l0r = 0.0f,  l1r = 0.0f;
    float o[8][4] = {};
    float* Pp = Ps + wid * 1024;

    const int ktiles = (q0 >> 6) + 2;
    const int maskStart = ktiles - 2;

    for (int kt = 0; kt < ktiles; kt++) {
        const int k0 = kt * 64;
        float* Ks = KsB + (kt & 1) * 4096;
        float* Vt = VtB + (kt & 1) * 4096;

        // load K/V tile (s[] is dead here; transient regs ok)
        float4 kr[4], vr[4];
        #pragma unroll
        for (int i = 0; i < 4; i++) {
            int idx = tid + i * 256;
            int c = idx >> 4, d4 = (idx & 15) * 4;
            kr[i] = *(const float4*)&Kg[(size_t)(k0 + c) * HD + d4];
            vr[i] = *(const float4*)&Vg[(size_t)(k0 + c) * HD + d4];
        }
        // store to current buffer (cvt + swizzle, patterns identical to best)
        #pragma unroll
        for (int i = 0; i < 4; i++) {
            int idx = tid + i * 256;
            int c = idx >> 4, d4 = (idx & 15) * 4;
            int kc = d4 >> 4, t = (d4 & 15) >> 2;
            int rkK = (((c >> 2) ^ kc)) & 3;
            float* kd = &Ks[(((kc << 6) + c) << 4) + t];
            kd[((0^rkK)<<2)] = tfbits(kr[i].x);
            kd[((1^rkK)<<2)] = tfbits(kr[i].y);
            kd[((2^rkK)<<2)] = tfbits(kr[i].z);
            kd[((3^rkK)<<2)] = tfbits(kr[i].w);
            int kcv = c >> 4, tv = (c & 15) >> 2;
            int qv = ((c & 3) ^ ((d4 >> 2) & 3) ^ kcv) & 3;
            float* vd = &Vt[(((kcv << 6) + d4) << 4) + (qv << 2) + tv];
            vd[0]  = tfbits(vr[i].x);
            vd[16] = tfbits(vr[i].y);
            vd[32] = tfbits(vr[i].z);
            vd[48] = tfbits(vr[i].w);
        }
        __syncthreads();             // SINGLE barrier per ktile (dbuf-safe)

        // S = Q K^T : warp computes 16x64 (Q from registers)
        float s[8][4] = {};
        #pragma unroll
        for (int kc = 0; kc < 4; kc++) {
            const unsigned* a0v = &Qr[kc][0];   // {qlo.x,qhi.x,qlo.y,qhi.y}
            const unsigned* a1v = &Qr[kc][4];
            #pragma unroll
            for (int ni = 0; ni < 8; ni++) {
                int n = ni * 8 + r4;
                int rkB = ((2 * ni + rk4) ^ kc) & 3;
                float4 bv = *(const float4*)&Ks[(((kc << 6) + n) << 4) + (((c4 ^ rkB) & 3) << 2)];
                unsigned b0v[2] = {U(bv.x), U(bv.y)};
                unsigned b1v[2] = {U(bv.z), U(bv.w)};
                mma8(s[ni], a0v, b0v);
                mma8(s[ni], a1v, b1v);
            }
        }

        // causal mask
        if (kt >= maskStart) {
            int grow = q0 + wid * 16 + r4;
            #pragma unroll
            for (int ni = 0; ni < 8; ni++) {
                int gcol = k0 + ni * 8 + c4 * 2;
                if (gcol     > grow    ) s[ni][0] = -1e30f;
                if (gcol + 1 > grow    ) s[ni][1] = -1e30f;
                if (gcol     > grow + 8) s[ni][2] = -1e30f;
                if (gcol + 1 > grow + 8) s[ni][3] = -1e30f;
            }
        }

        // online softmax (2 rows/thread, quad reduce)
        float mx0 = -1e30f, mx1 = -1e30f;
        #pragma unroll
        for (int ni = 0; ni < 8; ni++) {
            mx0 = fmaxf(mx0, fmaxf(s[ni][0], s[ni][1]));
            mx1 = fmaxf(mx1, fmaxf(s[ni][2], s[ni][3]));
        }
        mx0 = fmaxf(mx0, __shfl_xor_sync(0xffffffffu, mx0, 1));
        mx0 = fmaxf(mx0, __shfl_xor_sync(0xffffffffu, mx0, 2));
        mx1 = fmaxf(mx1, __shfl_xor_sync(0xffffffffu, mx1, 1));
        mx1 = fmaxf(mx1, __shfl_xor_sync(0xffffffffu, mx1, 2));
        float mn0 = fmaxf(m0r, mx0), mn1 = fmaxf(m1r, mx1);
        float al0 = __expf(m0r - mn0), al1 = __expf(m1r - mn1);
        float ls0 = 0.0f, ls1 = 0.0f;
        #pragma unroll
        for (int ni = 0; ni < 8; ni++) {
            s[ni][0] = __expf(s[ni][0] - mn0);
            s[ni][1] = __expf(s[ni][1] - mn0);
            s[ni][2] = __expf(s[ni][2] - mn1);
            s[ni][3] = __expf(s[ni][3] - mn1);
            ls0 += s[ni][0] + s[ni][1];
            ls1 += s[ni][2] + s[ni][3];
        }
        ls0 += __shfl_xor_sync(0xffffffffu, ls0, 1);
        ls0 += __shfl_xor_sync(0xffffffffu, ls0, 2);
        ls1 += __shfl_xor_sync(0xffffffffu, ls1, 1);
        ls1 += __shfl_xor_sync(0xffffffffu, ls1, 2);
        l0r = l0r * al0 + ls0;  m0r = mn0;
        l1r = l1r * al1 + ls1;  m1r = mn1;

        #pragma unroll
        for (int ni = 0; ni < 8; ni++) {
            o[ni][0] *= al0; o[ni][1] *= al0;
            o[ni][2] *= al1; o[ni][3] *= al1;
        }

        // stage P (tf32) fragment-native, per-warp region
        #pragma unroll
        for (int ni = 0; ni < 8; ni++) {
            int kc  = ni >> 1;
            int c16 = ((ni & 1) << 3) + (c4 << 1);
            int tP  = c16 >> 2;
            int ql = ((c16 & 3) ^ rk4 ^ kc) & 3;
            int qh = ql ^ 2;
            float* plo = &Pp[(((kc << 4) + r4) << 4) + tP];
            float* phi = plo + (8 << 4);
            plo[(ql      << 2)] = tfbits(s[ni][0]);
            plo[((ql ^ 1) << 2)] = tfbits(s[ni][1]);
            phi[(qh      << 2)] = tfbits(s[ni][2]);
            phi[((qh ^ 1) << 2)] = tfbits(s[ni][3]);
        }
        __syncwarp();

        // O += P @ V
        #pragma unroll
        for (int kc = 0; kc < 4; kc++) {
            int rkP = (rk4 ^ kc) & 3;
            float4 plo4 = *(const float4*)&Pp[((((kc << 4) + r4    ) << 4)) + (((c4 ^ rkP)     & 3) << 2)];
            float4 phi4 = *(const float4*)&Pp[((((kc << 4) + r4 + 8) << 4)) + (((c4 ^ rkP ^ 2) & 3) << 2)];
            unsigned a0v[4] = {U(plo4.x), U(phi4.x), U(plo4.y), U(phi4.y)};
            unsigned a1v[4] = {U(plo4.z), U(phi4.z), U(plo4.w), U(phi4.w)};
            #pragma unroll
            for (int ni = 0; ni < 8; ni++) {
                int n = ni * 8 + r4;
                int rkV = ((2 * ni + rk4) ^ kc) & 3;
                float4 bv = *(const float4*)&Vt[(((kc << 6) + n) << 4) + (((c4 ^ rkV) & 3) << 2)];
                unsigned b0v[2] = {U(bv.x), U(bv.y)};
                unsigned b1v[2] = {U(bv.z), U(bv.w)};
                mma8(o[ni], a0v, b0v);
                mma8(o[ni], a1v, b1v);
            }
        }
        __syncwarp();
    }

    // epilogue: divide by l, write to g_AO (b, n, h*64+d)
    float inv0 = 1.0f / l0r, inv1 = 1.0f / l1r;
    const int b = bh >> 3, h = bh & 7;
    const int row0 = q0 + wid * 16 + r4;
    #pragma unroll
    for (int ni = 0; ni < 8; ni++) {
        int e = h * 64 + ni * 8 + c4 * 2;
        *(float2*)&g_AO[(size_t)(b * SEQ + row0    ) * EMB + e] =
            make_float2(o[ni][0] * inv0, o[ni][1] * inv0);
        *(float2*)&g_AO[(size_t)(b * SEQ + row0 + 8) * EMB + e] =
            make_float2(o[ni][2] * inv1, o[ni][3] * inv1);
    }
}

// ---------------------------------------------------------------------------

extern "C" void kernel_launch(void* const* d_in, const int* in_sizes, int n_in,
                              void* d_out, int out_size)
{
    const float* x  = (const float*)d_in[0];
    const float* WQ = (const float*)d_in[1];
    const float* WK = (const float*)d_in[2];
    const float* WV = (const float*)d_in[3];
    const float* WO = (const float*)d_in[4];
    // d_in[5] = mask (tril) — causal, applied analytically in-kernel.
    float* out = (float*)d_out;

    const int SMEM_ATTN = 24576 * (int)sizeof(float);   // 96KB
    static bool attr_set = false;
    if (!attr_set) {
        cudaFuncSetAttribute(attn_tc,
                             cudaFuncAttributeMaxDynamicSharedMemorySize, SMEM_ATTN);
        attr_set = true;
    }

    gemm_qkv<<<dim3(EMB / 128, MROWS / 128, 3), 512>>>(x, WQ, WK, WV);

    attn_tc<<<dim3(BATCH * NH, SEQ / 128), 256, SMEM_ATTN>>>();

    gemm_out<<<dim3(EMB / 128, MROWS / 128), 512>>>(WO, out);
}